// round 1
// baseline (speedup 1.0000x reference)
#include <cuda_runtime.h>

#define N_NODES 100000
#define E_MSG   3200000
#define E_SC    1000000
#define IN_DIM  12
#define HID     64
#define EMB     32
#define EDGE_F  10
#define EDGE_REPR 74
#define D2PAD   76   // dec_W2 row padded to multiple of 4

// ---------------- scratch (static device globals; no allocation) -------------
__device__ float g_agg1[N_NODES * IN_DIM];
__device__ float g_cnt [N_NODES];
__device__ float g_h   [N_NODES * HID];
__device__ float g_agg2[N_NODES * HID];
__device__ float g_emb [N_NODES * EMB];

// ---------------- int32/int64 index handling ---------------------------------
// jax may silently demote int64->int32. Values are node ids < 1e5, so for a
// true int64 array every odd 32-bit word is 0. For an int32 array the odds of
// three random ids all being 0 is ~1e-15.
__device__ __forceinline__ bool idx_is64(const void* p) {
    const int* q = (const int*)p;
    return (q[1] | q[3] | q[5]) == 0;
}
__device__ __forceinline__ long long ld_idx(const void* p, long long i, bool is64) {
    if (is64) return ((const long long*)p)[i];
    return (long long)((const int*)p)[i];
}

__device__ __forceinline__ float warp_sum(float v) {
#pragma unroll
    for (int o = 16; o > 0; o >>= 1) v += __shfl_xor_sync(0xffffffffu, v, o);
    return v;
}

// ---------------- zero scratch ------------------------------------------------
__global__ __launch_bounds__(256) void zero_kernel() {
    int i = blockIdx.x * 256 + threadIdx.x;
    const int A1 = N_NODES * IN_DIM;           // 1.2M
    const int A2 = A1 + N_NODES;               // +0.1M
    const int A3 = A2 + N_NODES * HID;         // +6.4M
    if (i < A1)      g_agg1[i] = 0.f;
    else if (i < A2) g_cnt[i - A1] = 0.f;
    else if (i < A3) g_agg2[i - A2] = 0.f;
}

// ---------------- scatter layer-1 features + degree counts -------------------
__global__ __launch_bounds__(256) void scatter1_kernel(const void* __restrict__ ei,
                                                       const float* __restrict__ nf) {
    int e = blockIdx.x * 256 + threadIdx.x;
    if (e >= E_MSG) return;
    bool is64 = idx_is64(ei);
    long long s = ld_idx(ei, e, is64);
    long long d = ld_idx(ei, (long long)E_MSG + e, is64);
    const float* x = nf + s * IN_DIM;
    float* a = g_agg1 + d * IN_DIM;
#pragma unroll
    for (int k = 0; k < IN_DIM; k++) atomicAdd(a + k, x[k]);
    atomicAdd(g_cnt + d, 1.f);
}

// ---------------- SAGE layer 1: 12 -> 64 + LN + relu -------------------------
__global__ __launch_bounds__(256) void sage1_kernel(const float* __restrict__ nf,
                                                    const float* __restrict__ Ws,
                                                    const float* __restrict__ Wn,
                                                    const float* __restrict__ b,
                                                    const float* __restrict__ g,
                                                    const float* __restrict__ be) {
    __shared__ float sWs[IN_DIM * HID], sWn[IN_DIM * HID];
    __shared__ float sb[HID], sg[HID], sbe[HID];
    for (int i = threadIdx.x; i < IN_DIM * HID; i += 256) { sWs[i] = Ws[i]; sWn[i] = Wn[i]; }
    if (threadIdx.x < HID) {
        sb[threadIdx.x] = b[threadIdx.x];
        sg[threadIdx.x] = g[threadIdx.x];
        sbe[threadIdx.x] = be[threadIdx.x];
    }
    __syncthreads();
    int n = blockIdx.x * 8 + (threadIdx.x >> 5);   // 12500 blocks * 8 warps = 100000
    int lane = threadIdx.x & 31;
    float inv = 1.f / fmaxf(g_cnt[n], 1.f);
    float h0 = sb[lane], h1 = sb[lane + 32];
#pragma unroll
    for (int k = 0; k < IN_DIM; k++) {
        float xk = nf[n * IN_DIM + k];
        float ak = g_agg1[n * IN_DIM + k] * inv;
        h0 += xk * sWs[k * HID + lane]      + ak * sWn[k * HID + lane];
        h1 += xk * sWs[k * HID + lane + 32] + ak * sWn[k * HID + lane + 32];
    }
    float s1 = warp_sum(h0 + h1);
    float s2 = warp_sum(h0 * h0 + h1 * h1);
    float mu  = s1 * (1.f / 64.f);
    float var = s2 * (1.f / 64.f) - mu * mu;
    float r = rsqrtf(var + 1e-5f);
    g_h[n * HID + lane]      = fmaxf((h0 - mu) * r * sg[lane]      + sbe[lane],      0.f);
    g_h[n * HID + lane + 32] = fmaxf((h1 - mu) * r * sg[lane + 32] + sbe[lane + 32], 0.f);
}

// ---------------- scatter layer-2 features (h[src] -> agg2[dst]) -------------
__global__ __launch_bounds__(256) void scatter2_kernel(const void* __restrict__ ei) {
    int gid = blockIdx.x * 256 + threadIdx.x;
    int e = gid >> 5;
    int t = gid & 31;
    if (e >= E_MSG) return;
    bool is64 = idx_is64(ei);
    long long s = ld_idx(ei, e, is64);
    long long d = ld_idx(ei, (long long)E_MSG + e, is64);
    atomicAdd(g_agg2 + d * HID + t,      g_h[s * HID + t]);
    atomicAdd(g_agg2 + d * HID + 32 + t, g_h[s * HID + 32 + t]);
}

// ---------------- SAGE layer 2: 64 -> 32 + LN + relu -------------------------
__global__ __launch_bounds__(256) void sage2_kernel(const float* __restrict__ Ws,
                                                    const float* __restrict__ Wn,
                                                    const float* __restrict__ b,
                                                    const float* __restrict__ g,
                                                    const float* __restrict__ be) {
    __shared__ float sWs[HID * EMB], sWn[HID * EMB];
    __shared__ float sb[EMB], sg[EMB], sbe[EMB];
    for (int i = threadIdx.x; i < HID * EMB; i += 256) { sWs[i] = Ws[i]; sWn[i] = Wn[i]; }
    if (threadIdx.x < EMB) {
        sb[threadIdx.x] = b[threadIdx.x];
        sg[threadIdx.x] = g[threadIdx.x];
        sbe[threadIdx.x] = be[threadIdx.x];
    }
    __syncthreads();
    int n = blockIdx.x * 8 + (threadIdx.x >> 5);
    int lane = threadIdx.x & 31;
    float inv = 1.f / fmaxf(g_cnt[n], 1.f);
    float hl = g_h[n * HID + lane];
    float hh = g_h[n * HID + 32 + lane];
    float al = g_agg2[n * HID + lane] * inv;
    float ah = g_agg2[n * HID + 32 + lane] * inv;
    float acc = sb[lane];
#pragma unroll
    for (int k = 0; k < 32; k++) {
        float hk = __shfl_sync(0xffffffffu, hl, k);
        float ak = __shfl_sync(0xffffffffu, al, k);
        acc += hk * sWs[k * EMB + lane] + ak * sWn[k * EMB + lane];
    }
#pragma unroll
    for (int k = 0; k < 32; k++) {
        float hk = __shfl_sync(0xffffffffu, hh, k);
        float ak = __shfl_sync(0xffffffffu, ah, k);
        acc += hk * sWs[(k + 32) * EMB + lane] + ak * sWn[(k + 32) * EMB + lane];
    }
    float s1 = warp_sum(acc);
    float s2 = warp_sum(acc * acc);
    float mu  = s1 * (1.f / 32.f);
    float var = s2 * (1.f / 32.f) - mu * mu;
    float r = rsqrtf(var + 1e-5f);
    g_emb[n * EMB + lane] = fmaxf((acc - mu) * r * sg[lane] + sbe[lane], 0.f);
}

// ---------------- edge_rep writer (coalesced) --------------------------------
__global__ __launch_bounds__(256) void edge_rep_kernel(const void* __restrict__ srcn,
                                                       const void* __restrict__ dstn,
                                                       const float* __restrict__ ea,
                                                       float* __restrict__ out_er) {
    int i = blockIdx.x * 256 + threadIdx.x;
    if (i >= E_SC * EDGE_REPR) return;
    int e = i / EDGE_REPR;
    int c = i - e * EDGE_REPR;
    bool is64s = idx_is64(srcn);
    bool is64d = idx_is64(dstn);
    float v;
    if (c < EMB) {
        long long s = ld_idx(srcn, e, is64s);
        v = g_emb[s * EMB + c];
    } else if (c < 2 * EMB) {
        long long d = ld_idx(dstn, e, is64d);
        v = g_emb[d * EMB + (c - EMB)];
    } else {
        v = ea[(long long)e * EDGE_F + (c - 2 * EMB)];
    }
    out_er[i] = v;
}

// ---------------- edge MLP: 74 -> 64 -> 32 -> 64 -> 74 -----------------------
// Shared layout (floats): W1(74*64) W2(64*32) D1(32*64) D2(64*76) b1(64) b2(32) b3(64) b4(76)
#define SM_W1 0
#define SM_W2 (SM_W1 + EDGE_REPR * HID)
#define SM_D1 (SM_W2 + HID * EMB)
#define SM_D2 (SM_D1 + EMB * HID)
#define SM_B1 (SM_D2 + HID * D2PAD)
#define SM_B2 (SM_B1 + HID)
#define SM_B3 (SM_B2 + EMB)
#define SM_B4 (SM_B3 + HID)
#define SM_TOTAL (SM_B4 + D2PAD)   // 13932 floats = 55728 B

__global__ __launch_bounds__(256) void edge_mlp_kernel(
    const void* __restrict__ srcn, const void* __restrict__ dstn,
    const float* __restrict__ ea,
    const float* __restrict__ eW1, const float* __restrict__ eb1,
    const float* __restrict__ eW2, const float* __restrict__ eb2,
    const float* __restrict__ dW1, const float* __restrict__ db1,
    const float* __restrict__ dW2, const float* __restrict__ db2,
    float* __restrict__ out_recon) {
    extern __shared__ float sm[];
    for (int i = threadIdx.x; i < EDGE_REPR * HID; i += 256) sm[SM_W1 + i] = eW1[i];
    for (int i = threadIdx.x; i < HID * EMB; i += 256)       sm[SM_W2 + i] = eW2[i];
    for (int i = threadIdx.x; i < EMB * HID; i += 256)       sm[SM_D1 + i] = dW1[i];
    for (int i = threadIdx.x; i < HID * D2PAD; i += 256) {
        int k = i / D2PAD, j = i - k * D2PAD;
        sm[SM_D2 + i] = (j < EDGE_REPR) ? dW2[k * EDGE_REPR + j] : 0.f;
    }
    for (int i = threadIdx.x; i < HID; i += 256)   { sm[SM_B1 + i] = eb1[i]; sm[SM_B3 + i] = db1[i]; }
    for (int i = threadIdx.x; i < EMB; i += 256)     sm[SM_B2 + i] = eb2[i];
    for (int i = threadIdx.x; i < D2PAD; i += 256)   sm[SM_B4 + i] = (i < EDGE_REPR) ? db2[i] : 0.f;
    __syncthreads();

    int e = blockIdx.x * 256 + threadIdx.x;
    if (e >= E_SC) return;
    bool is64s = idx_is64(srcn);
    bool is64d = idx_is64(dstn);
    long long s = ld_idx(srcn, e, is64s);
    long long d = ld_idx(dstn, e, is64d);

    float er[EDGE_REPR];
#pragma unroll
    for (int i = 0; i < EMB; i++) er[i]       = g_emb[s * EMB + i];
#pragma unroll
    for (int i = 0; i < EMB; i++) er[EMB + i] = g_emb[d * EMB + i];
#pragma unroll
    for (int i = 0; i < EDGE_F; i++) er[2 * EMB + i] = ea[(long long)e * EDGE_F + i];

    // enc1: 74 -> 64, relu
    float r1[HID];
#pragma unroll
    for (int j = 0; j < HID; j++) r1[j] = sm[SM_B1 + j];
#pragma unroll
    for (int k = 0; k < EDGE_REPR; k++) {
        float ek = er[k];
        const float4* w = (const float4*)(sm + SM_W1 + k * HID);
#pragma unroll
        for (int j = 0; j < HID / 4; j++) {
            float4 v = w[j];
            r1[4 * j]     += ek * v.x;
            r1[4 * j + 1] += ek * v.y;
            r1[4 * j + 2] += ek * v.z;
            r1[4 * j + 3] += ek * v.w;
        }
    }
#pragma unroll
    for (int j = 0; j < HID; j++) r1[j] = fmaxf(r1[j], 0.f);

    // enc2: 64 -> 32, relu
    float lat[EMB];
#pragma unroll
    for (int j = 0; j < EMB; j++) lat[j] = sm[SM_B2 + j];
#pragma unroll
    for (int k = 0; k < HID; k++) {
        float rk = r1[k];
        const float4* w = (const float4*)(sm + SM_W2 + k * EMB);
#pragma unroll
        for (int j = 0; j < EMB / 4; j++) {
            float4 v = w[j];
            lat[4 * j]     += rk * v.x;
            lat[4 * j + 1] += rk * v.y;
            lat[4 * j + 2] += rk * v.z;
            lat[4 * j + 3] += rk * v.w;
        }
    }
#pragma unroll
    for (int j = 0; j < EMB; j++) lat[j] = fmaxf(lat[j], 0.f);

    // dec1: 32 -> 64, relu
    float h2[HID];
#pragma unroll
    for (int j = 0; j < HID; j++) h2[j] = sm[SM_B3 + j];
#pragma unroll
    for (int k = 0; k < EMB; k++) {
        float lk = lat[k];
        const float4* w = (const float4*)(sm + SM_D1 + k * HID);
#pragma unroll
        for (int j = 0; j < HID / 4; j++) {
            float4 v = w[j];
            h2[4 * j]     += lk * v.x;
            h2[4 * j + 1] += lk * v.y;
            h2[4 * j + 2] += lk * v.z;
            h2[4 * j + 3] += lk * v.w;
        }
    }
#pragma unroll
    for (int j = 0; j < HID; j++) h2[j] = fmaxf(h2[j], 0.f);

    // dec2: 64 -> 74 (padded 76), no relu
    float rec[D2PAD];
#pragma unroll
    for (int j = 0; j < D2PAD; j++) rec[j] = sm[SM_B4 + j];
#pragma unroll
    for (int k = 0; k < HID; k++) {
        float hk = h2[k];
        const float4* w = (const float4*)(sm + SM_D2 + k * D2PAD);
#pragma unroll
        for (int j = 0; j < D2PAD / 4; j++) {
            float4 v = w[j];
            rec[4 * j]     += hk * v.x;
            rec[4 * j + 1] += hk * v.y;
            rec[4 * j + 2] += hk * v.z;
            rec[4 * j + 3] += hk * v.w;
        }
    }
    float* o = out_recon + (long long)e * EDGE_REPR;
#pragma unroll
    for (int j = 0; j < EDGE_REPR; j++) o[j] = rec[j];
}

// ---------------- launcher ----------------------------------------------------
extern "C" void kernel_launch(void* const* d_in, const int* in_sizes, int n_in,
                              void* d_out, int out_size) {
    const float* nf   = (const float*)d_in[0];
    const void*  ei   = d_in[1];
    const float* ea   = (const float*)d_in[2];
    const void*  srcn = d_in[3];
    const void*  dstn = d_in[4];
    const float* Ws1 = (const float*)d_in[5];
    const float* Wn1 = (const float*)d_in[6];
    const float* b1  = (const float*)d_in[7];
    const float* g1  = (const float*)d_in[8];
    const float* be1 = (const float*)d_in[9];
    const float* Ws2 = (const float*)d_in[10];
    const float* Wn2 = (const float*)d_in[11];
    const float* b2  = (const float*)d_in[12];
    const float* g2  = (const float*)d_in[13];
    const float* be2 = (const float*)d_in[14];
    const float* eW1 = (const float*)d_in[15];
    const float* eb1 = (const float*)d_in[16];
    const float* eW2 = (const float*)d_in[17];
    const float* eb2 = (const float*)d_in[18];
    const float* dW1 = (const float*)d_in[19];
    const float* db1 = (const float*)d_in[20];
    const float* dW2 = (const float*)d_in[21];
    const float* db2 = (const float*)d_in[22];

    float* out_recon = (float*)d_out;                                   // [1M, 74]
    float* out_er    = (float*)d_out + (long long)E_SC * EDGE_REPR;     // [1M, 74]

    const int smem_mlp = SM_TOTAL * sizeof(float);  // 55728 B
    cudaFuncSetAttribute(edge_mlp_kernel, cudaFuncAttributeMaxDynamicSharedMemorySize, smem_mlp);

    const int zero_total = N_NODES * IN_DIM + N_NODES + N_NODES * HID;
    zero_kernel<<<(zero_total + 255) / 256, 256>>>();
    scatter1_kernel<<<(E_MSG + 255) / 256, 256>>>(ei, nf);
    sage1_kernel<<<N_NODES / 8, 256>>>(nf, Ws1, Wn1, b1, g1, be1);
    scatter2_kernel<<<(E_MSG * 32) / 256, 256>>>(ei);
    sage2_kernel<<<N_NODES / 8, 256>>>(Ws2, Wn2, b2, g2, be2);
    edge_rep_kernel<<<(E_SC * EDGE_REPR + 255) / 256, 256>>>(srcn, dstn, ea, out_er);
    edge_mlp_kernel<<<(E_SC + 255) / 256, 256, smem_mlp>>>(
        srcn, dstn, ea, eW1, eb1, eW2, eb2, dW1, db1, dW2, db2, out_recon);
}

// round 2
// speedup vs baseline: 1.8453x; 1.8453x over previous
#include <cuda_runtime.h>

#define N_NODES 100000
#define E_MSG   3200000
#define E_SC    1000000
#define IN_DIM  12
#define HID     64
#define EMB     32
#define EDGE_F  10
#define EDGE_REPR 74
#define D2PAD   76   // dec_W2 row padded to multiple of 4

// ---------------- scratch (static device globals; no allocation) -------------
__device__ float g_agg1 [N_NODES * IN_DIM];
__device__ float g_cnt  [N_NODES];
__device__ float g_h    [N_NODES * HID];
__device__ float g_p    [N_NODES * EMB];   // h @ Wn2 (projected, 32-dim)
__device__ float g_agg2p[N_NODES * EMB];   // scatter of g_p
__device__ float g_emb  [N_NODES * EMB];

// ---------------- int32/int64 index handling ---------------------------------
__device__ __forceinline__ bool idx_is64(const void* p) {
    const int* q = (const int*)p;
    return (q[1] | q[3] | q[5]) == 0;
}
__device__ __forceinline__ long long ld_idx(const void* p, long long i, bool is64) {
    if (is64) return ((const long long*)p)[i];
    return (long long)((const int*)p)[i];
}

__device__ __forceinline__ float warp_sum(float v) {
#pragma unroll
    for (int o = 16; o > 0; o >>= 1) v += __shfl_xor_sync(0xffffffffu, v, o);
    return v;
}

// ---------------- packed f32x2 helpers (sm_100+) ------------------------------
__device__ __forceinline__ unsigned long long pk2(float a, float b) {
    unsigned long long r;
    asm("mov.b64 %0, {%1,%2};" : "=l"(r) : "f"(a), "f"(b));
    return r;
}
__device__ __forceinline__ void upk2(unsigned long long p, float& a, float& b) {
    asm("mov.b64 {%0,%1}, %2;" : "=f"(a), "=f"(b) : "l"(p));
}
__device__ __forceinline__ void fma2(unsigned long long& d,
                                     unsigned long long a, unsigned long long b) {
    asm("fma.rn.f32x2 %0, %1, %2, %0;" : "+l"(d) : "l"(a), "l"(b));
}

// ---------------- vector float atomic (sm_90+) --------------------------------
__device__ __forceinline__ void red_add_v4(float* addr, float4 v) {
    asm volatile("red.global.add.v4.f32 [%0], {%1,%2,%3,%4};"
                 :: "l"(addr), "f"(v.x), "f"(v.y), "f"(v.z), "f"(v.w) : "memory");
}

// ---------------- zero scratch ------------------------------------------------
__global__ __launch_bounds__(256) void zero_kernel() {
    int i = blockIdx.x * 256 + threadIdx.x;
    const int A1 = N_NODES * IN_DIM;            // 1.2M
    const int A2 = A1 + N_NODES;                // +0.1M
    const int A3 = A2 + N_NODES * EMB;          // +3.2M
    if (i < A1)      g_agg1[i] = 0.f;
    else if (i < A2) g_cnt[i - A1] = 0.f;
    else if (i < A3) g_agg2p[i - A2] = 0.f;
}

// ---------------- scatter layer-1 features + degree counts -------------------
__global__ __launch_bounds__(256) void scatter1_kernel(const void* __restrict__ ei,
                                                       const float* __restrict__ nf) {
    int e = blockIdx.x * 256 + threadIdx.x;
    if (e >= E_MSG) return;
    bool is64 = idx_is64(ei);
    long long s = ld_idx(ei, e, is64);
    long long d = ld_idx(ei, (long long)E_MSG + e, is64);
    const float4* x = (const float4*)(nf + s * IN_DIM);   // 48B rows, 16B aligned
    float* a = g_agg1 + d * IN_DIM;
#pragma unroll
    for (int j = 0; j < 3; j++) red_add_v4(a + 4 * j, x[j]);
    atomicAdd(g_cnt + d, 1.f);
}

// ---------------- SAGE layer 1: 12 -> 64 + LN + relu -------------------------
__global__ __launch_bounds__(256) void sage1_kernel(const float* __restrict__ nf,
                                                    const float* __restrict__ Ws,
                                                    const float* __restrict__ Wn,
                                                    const float* __restrict__ b,
                                                    const float* __restrict__ g,
                                                    const float* __restrict__ be) {
    __shared__ float sWs[IN_DIM * HID], sWn[IN_DIM * HID];
    __shared__ float sb[HID], sg[HID], sbe[HID];
    for (int i = threadIdx.x; i < IN_DIM * HID; i += 256) { sWs[i] = Ws[i]; sWn[i] = Wn[i]; }
    if (threadIdx.x < HID) {
        sb[threadIdx.x] = b[threadIdx.x];
        sg[threadIdx.x] = g[threadIdx.x];
        sbe[threadIdx.x] = be[threadIdx.x];
    }
    __syncthreads();
    int n = blockIdx.x * 8 + (threadIdx.x >> 5);
    int lane = threadIdx.x & 31;
    float inv = 1.f / fmaxf(g_cnt[n], 1.f);
    float h0 = sb[lane], h1 = sb[lane + 32];
#pragma unroll
    for (int k = 0; k < IN_DIM; k++) {
        float xk = nf[n * IN_DIM + k];
        float ak = g_agg1[n * IN_DIM + k] * inv;
        h0 += xk * sWs[k * HID + lane]      + ak * sWn[k * HID + lane];
        h1 += xk * sWs[k * HID + lane + 32] + ak * sWn[k * HID + lane + 32];
    }
    float s1 = warp_sum(h0 + h1);
    float s2 = warp_sum(h0 * h0 + h1 * h1);
    float mu  = s1 * (1.f / 64.f);
    float var = s2 * (1.f / 64.f) - mu * mu;
    float r = rsqrtf(var + 1e-5f);
    g_h[n * HID + lane]      = fmaxf((h0 - mu) * r * sg[lane]      + sbe[lane],      0.f);
    g_h[n * HID + lane + 32] = fmaxf((h1 - mu) * r * sg[lane + 32] + sbe[lane + 32], 0.f);
}

// ---------------- project h -> p = h @ Wn2  (100K x 64 x 32) ------------------
__global__ __launch_bounds__(256) void proj2_kernel(const float* __restrict__ Wn) {
    __shared__ float sW[HID * EMB];
    for (int i = threadIdx.x; i < HID * EMB; i += 256) sW[i] = Wn[i];
    __syncthreads();
    int n = blockIdx.x * 8 + (threadIdx.x >> 5);
    int lane = threadIdx.x & 31;
    float hl = g_h[n * HID + lane];
    float hh = g_h[n * HID + 32 + lane];
    float acc = 0.f;
#pragma unroll
    for (int k = 0; k < 32; k++)
        acc += __shfl_sync(0xffffffffu, hl, k) * sW[k * EMB + lane];
#pragma unroll
    for (int k = 0; k < 32; k++)
        acc += __shfl_sync(0xffffffffu, hh, k) * sW[(k + 32) * EMB + lane];
    g_p[n * EMB + lane] = acc;
}

// ---------------- scatter layer-2 (projected): p[src] -> agg2p[dst] ----------
__global__ __launch_bounds__(256) void scatter2_kernel(const void* __restrict__ ei) {
    int e = blockIdx.x * 256 + threadIdx.x;
    if (e >= E_MSG) return;
    bool is64 = idx_is64(ei);
    long long s = ld_idx(ei, e, is64);
    long long d = ld_idx(ei, (long long)E_MSG + e, is64);
    const float4* ps = (const float4*)(g_p + s * EMB);    // 128B rows
    float* pd = g_agg2p + d * EMB;
#pragma unroll
    for (int j = 0; j < 8; j++) red_add_v4(pd + 4 * j, ps[j]);
}

// ---------------- SAGE layer 2: 64 -> 32 + LN + relu -------------------------
__global__ __launch_bounds__(256) void sage2_kernel(const float* __restrict__ Ws,
                                                    const float* __restrict__ b,
                                                    const float* __restrict__ g,
                                                    const float* __restrict__ be) {
    __shared__ float sWs[HID * EMB];
    __shared__ float sb[EMB], sg[EMB], sbe[EMB];
    for (int i = threadIdx.x; i < HID * EMB; i += 256) sWs[i] = Ws[i];
    if (threadIdx.x < EMB) {
        sb[threadIdx.x] = b[threadIdx.x];
        sg[threadIdx.x] = g[threadIdx.x];
        sbe[threadIdx.x] = be[threadIdx.x];
    }
    __syncthreads();
    int n = blockIdx.x * 8 + (threadIdx.x >> 5);
    int lane = threadIdx.x & 31;
    float inv = 1.f / fmaxf(g_cnt[n], 1.f);
    float hl = g_h[n * HID + lane];
    float hh = g_h[n * HID + 32 + lane];
    float acc = sb[lane] + g_agg2p[n * EMB + lane] * inv;
#pragma unroll
    for (int k = 0; k < 32; k++)
        acc += __shfl_sync(0xffffffffu, hl, k) * sWs[k * EMB + lane];
#pragma unroll
    for (int k = 0; k < 32; k++)
        acc += __shfl_sync(0xffffffffu, hh, k) * sWs[(k + 32) * EMB + lane];
    float s1 = warp_sum(acc);
    float s2 = warp_sum(acc * acc);
    float mu  = s1 * (1.f / 32.f);
    float var = s2 * (1.f / 32.f) - mu * mu;
    float r = rsqrtf(var + 1e-5f);
    g_emb[n * EMB + lane] = fmaxf((acc - mu) * r * sg[lane] + sbe[lane], 0.f);
}

// ---------------- fused edge_rep + edge MLP (packed f32x2) -------------------
// Shared layout (floats): W1(74*64) W2(64*32) D1(32*64) D2(64*76) b1(64) b2(32) b3(64) b4(76)
#define SM_W1 0
#define SM_W2 (SM_W1 + EDGE_REPR * HID)
#define SM_D1 (SM_W2 + HID * EMB)
#define SM_D2 (SM_D1 + EMB * HID)
#define SM_B1 (SM_D2 + HID * D2PAD)
#define SM_B2 (SM_B1 + HID)
#define SM_B3 (SM_B2 + EMB)
#define SM_B4 (SM_B3 + HID)
#define SM_TOTAL (SM_B4 + D2PAD)   // 13932 floats = 55728 B

#define MLP_THREADS 128

__global__ __launch_bounds__(MLP_THREADS, 3) void edge_mlp_kernel(
    const void* __restrict__ srcn, const void* __restrict__ dstn,
    const float* __restrict__ ea,
    const float* __restrict__ eW1, const float* __restrict__ eb1,
    const float* __restrict__ eW2, const float* __restrict__ eb2,
    const float* __restrict__ dW1, const float* __restrict__ db1,
    const float* __restrict__ dW2, const float* __restrict__ db2,
    float* __restrict__ out_recon, float* __restrict__ out_er) {
    extern __shared__ float sm[];
    for (int i = threadIdx.x; i < EDGE_REPR * HID; i += MLP_THREADS) sm[SM_W1 + i] = eW1[i];
    for (int i = threadIdx.x; i < HID * EMB; i += MLP_THREADS)       sm[SM_W2 + i] = eW2[i];
    for (int i = threadIdx.x; i < EMB * HID; i += MLP_THREADS)       sm[SM_D1 + i] = dW1[i];
    for (int i = threadIdx.x; i < HID * D2PAD; i += MLP_THREADS) {
        int k = i / D2PAD, j = i - k * D2PAD;
        sm[SM_D2 + i] = (j < EDGE_REPR) ? dW2[k * EDGE_REPR + j] : 0.f;
    }
    for (int i = threadIdx.x; i < HID; i += MLP_THREADS) { sm[SM_B1 + i] = eb1[i]; sm[SM_B3 + i] = db1[i]; }
    for (int i = threadIdx.x; i < EMB; i += MLP_THREADS)   sm[SM_B2 + i] = eb2[i];
    for (int i = threadIdx.x; i < D2PAD; i += MLP_THREADS) sm[SM_B4 + i] = (i < EDGE_REPR) ? db2[i] : 0.f;
    __syncthreads();

    int e = blockIdx.x * MLP_THREADS + threadIdx.x;
    if (e >= E_SC) return;
    bool is64s = idx_is64(srcn);
    bool is64d = idx_is64(dstn);
    long long s = ld_idx(srcn, e, is64s);
    long long d = ld_idx(dstn, e, is64d);

    // -------- gather edge representation --------
    float er[EDGE_REPR];
    {
        const float4* es = (const float4*)(g_emb + s * EMB);
        const float4* ed = (const float4*)(g_emb + d * EMB);
#pragma unroll
        for (int j = 0; j < 8; j++) {
            float4 v = es[j];
            er[4 * j] = v.x; er[4 * j + 1] = v.y; er[4 * j + 2] = v.z; er[4 * j + 3] = v.w;
        }
#pragma unroll
        for (int j = 0; j < 8; j++) {
            float4 v = ed[j];
            er[EMB + 4 * j] = v.x; er[EMB + 4 * j + 1] = v.y;
            er[EMB + 4 * j + 2] = v.z; er[EMB + 4 * j + 3] = v.w;
        }
#pragma unroll
        for (int i = 0; i < EDGE_F; i++) er[2 * EMB + i] = ea[(long long)e * EDGE_F + i];
    }
    // write edge_rep output (8B aligned: e*74*4 % 8 == 0)
    {
        unsigned long long* o = (unsigned long long*)(out_er + (long long)e * EDGE_REPR);
#pragma unroll
        for (int j = 0; j < EDGE_REPR / 2; j++) o[j] = pk2(er[2 * j], er[2 * j + 1]);
    }

    // -------- enc1: 74 -> 64, relu (packed pairs over output dim) --------
    unsigned long long a1[HID / 2];
    {
        const unsigned long long* bp = (const unsigned long long*)(sm + SM_B1);
#pragma unroll
        for (int j = 0; j < HID / 2; j++) a1[j] = bp[j];
#pragma unroll
        for (int k = 0; k < EDGE_REPR; k++) {
            unsigned long long ek = pk2(er[k], er[k]);
            const ulonglong2* w = (const ulonglong2*)(sm + SM_W1 + k * HID);
#pragma unroll
            for (int j = 0; j < HID / 4; j++) {
                ulonglong2 t = w[j];
                fma2(a1[2 * j], ek, t.x);
                fma2(a1[2 * j + 1], ek, t.y);
            }
        }
    }
    float r1[HID];
#pragma unroll
    for (int j = 0; j < HID / 2; j++) upk2(a1[j], r1[2 * j], r1[2 * j + 1]);
#pragma unroll
    for (int j = 0; j < HID; j++) r1[j] = fmaxf(r1[j], 0.f);

    // -------- enc2: 64 -> 32, relu --------
    unsigned long long a2[EMB / 2];
    {
        const unsigned long long* bp = (const unsigned long long*)(sm + SM_B2);
#pragma unroll
        for (int j = 0; j < EMB / 2; j++) a2[j] = bp[j];
#pragma unroll
        for (int k = 0; k < HID; k++) {
            unsigned long long rk = pk2(r1[k], r1[k]);
            const ulonglong2* w = (const ulonglong2*)(sm + SM_W2 + k * EMB);
#pragma unroll
            for (int j = 0; j < EMB / 4; j++) {
                ulonglong2 t = w[j];
                fma2(a2[2 * j], rk, t.x);
                fma2(a2[2 * j + 1], rk, t.y);
            }
        }
    }
    float lat[EMB];
#pragma unroll
    for (int j = 0; j < EMB / 2; j++) upk2(a2[j], lat[2 * j], lat[2 * j + 1]);
#pragma unroll
    for (int j = 0; j < EMB; j++) lat[j] = fmaxf(lat[j], 0.f);

    // -------- dec1: 32 -> 64, relu --------
    unsigned long long a3[HID / 2];
    {
        const unsigned long long* bp = (const unsigned long long*)(sm + SM_B3);
#pragma unroll
        for (int j = 0; j < HID / 2; j++) a3[j] = bp[j];
#pragma unroll
        for (int k = 0; k < EMB; k++) {
            unsigned long long lk = pk2(lat[k], lat[k]);
            const ulonglong2* w = (const ulonglong2*)(sm + SM_D1 + k * HID);
#pragma unroll
            for (int j = 0; j < HID / 4; j++) {
                ulonglong2 t = w[j];
                fma2(a3[2 * j], lk, t.x);
                fma2(a3[2 * j + 1], lk, t.y);
            }
        }
    }
    float h2[HID];
#pragma unroll
    for (int j = 0; j < HID / 2; j++) upk2(a3[j], h2[2 * j], h2[2 * j + 1]);
#pragma unroll
    for (int j = 0; j < HID; j++) h2[j] = fmaxf(h2[j], 0.f);

    // -------- dec2: 64 -> 74 (padded 76), no relu --------
    unsigned long long a4[D2PAD / 2];
    {
        const unsigned long long* bp = (const unsigned long long*)(sm + SM_B4);
#pragma unroll
        for (int j = 0; j < D2PAD / 2; j++) a4[j] = bp[j];
#pragma unroll
        for (int k = 0; k < HID; k++) {
            unsigned long long hk = pk2(h2[k], h2[k]);
            const ulonglong2* w = (const ulonglong2*)(sm + SM_D2 + k * D2PAD);
#pragma unroll
            for (int j = 0; j < D2PAD / 4; j++) {
                ulonglong2 t = w[j];
                fma2(a4[2 * j], hk, t.x);
                fma2(a4[2 * j + 1], hk, t.y);
            }
        }
    }
    {
        unsigned long long* o = (unsigned long long*)(out_recon + (long long)e * EDGE_REPR);
#pragma unroll
        for (int j = 0; j < EDGE_REPR / 2; j++) o[j] = a4[j];  // pairs 0..36 = cols 0..73
    }
}

// ---------------- launcher ----------------------------------------------------
extern "C" void kernel_launch(void* const* d_in, const int* in_sizes, int n_in,
                              void* d_out, int out_size) {
    const float* nf   = (const float*)d_in[0];
    const void*  ei   = d_in[1];
    const float* ea   = (const float*)d_in[2];
    const void*  srcn = d_in[3];
    const void*  dstn = d_in[4];
    const float* Ws1 = (const float*)d_in[5];
    const float* Wn1 = (const float*)d_in[6];
    const float* b1  = (const float*)d_in[7];
    const float* g1  = (const float*)d_in[8];
    const float* be1 = (const float*)d_in[9];
    const float* Ws2 = (const float*)d_in[10];
    const float* Wn2 = (const float*)d_in[11];
    const float* b2  = (const float*)d_in[12];
    const float* g2  = (const float*)d_in[13];
    const float* be2 = (const float*)d_in[14];
    const float* eW1 = (const float*)d_in[15];
    const float* eb1 = (const float*)d_in[16];
    const float* eW2 = (const float*)d_in[17];
    const float* eb2 = (const float*)d_in[18];
    const float* dW1 = (const float*)d_in[19];
    const float* db1 = (const float*)d_in[20];
    const float* dW2 = (const float*)d_in[21];
    const float* db2 = (const float*)d_in[22];

    float* out_recon = (float*)d_out;                                   // [1M, 74]
    float* out_er    = (float*)d_out + (long long)E_SC * EDGE_REPR;     // [1M, 74]

    const int smem_mlp = SM_TOTAL * sizeof(float);  // 55728 B
    cudaFuncSetAttribute(edge_mlp_kernel, cudaFuncAttributeMaxDynamicSharedMemorySize, smem_mlp);

    const int zero_total = N_NODES * IN_DIM + N_NODES + N_NODES * EMB;
    zero_kernel<<<(zero_total + 255) / 256, 256>>>();
    scatter1_kernel<<<(E_MSG + 255) / 256, 256>>>(ei, nf);
    sage1_kernel<<<N_NODES / 8, 256>>>(nf, Ws1, Wn1, b1, g1, be1);
    proj2_kernel<<<N_NODES / 8, 256>>>(Wn2);
    scatter2_kernel<<<(E_MSG + 255) / 256, 256>>>(ei);
    sage2_kernel<<<N_NODES / 8, 256>>>(Ws2, b2, g2, be2);
    edge_mlp_kernel<<<(E_SC + MLP_THREADS - 1) / MLP_THREADS, MLP_THREADS, smem_mlp>>>(
        srcn, dstn, ea, eW1, eb1, eW2, eb2, dW1, db1, dW2, db2, out_recon, out_er);
}

// round 4
// speedup vs baseline: 1.8681x; 1.0123x over previous
#include <cuda_runtime.h>

#define N_NODES 100000
#define E_MSG   3200000
#define E_SC    1000000
#define IN_DIM  12
#define HID     64
#define EMB     32
#define EDGE_F  10
#define EDGE_REPR 74
#define D2PAD   76   // dec_W2 row padded to multiple of 4

// ---------------- scratch (static device globals; no allocation) -------------
__device__ float g_agg1 [N_NODES * IN_DIM];
__device__ float g_cnt  [N_NODES];
__device__ float g_h    [N_NODES * HID];
__device__ float g_p    [N_NODES * EMB];   // h @ Wn2 (projected, 32-dim)
__device__ float g_agg2p[N_NODES * EMB];   // scatter of g_p
__device__ float g_emb  [N_NODES * EMB];

// ---------------- int32/int64 index handling ---------------------------------
__device__ __forceinline__ bool idx_is64(const void* p) {
    const int* q = (const int*)p;
    return (q[1] | q[3] | q[5]) == 0;
}
__device__ __forceinline__ long long ld_idx(const void* p, long long i, bool is64) {
    if (is64) return ((const long long*)p)[i];
    return (long long)((const int*)p)[i];
}

__device__ __forceinline__ float warp_sum(float v) {
#pragma unroll
    for (int o = 16; o > 0; o >>= 1) v += __shfl_xor_sync(0xffffffffu, v, o);
    return v;
}

// ---------------- packed f32x2 helpers (sm_100+) ------------------------------
__device__ __forceinline__ unsigned long long pk2(float a, float b) {
    unsigned long long r;
    asm("mov.b64 %0, {%1,%2};" : "=l"(r) : "f"(a), "f"(b));
    return r;
}
__device__ __forceinline__ void upk2(unsigned long long p, float& a, float& b) {
    asm("mov.b64 {%0,%1}, %2;" : "=f"(a), "=f"(b) : "l"(p));
}
__device__ __forceinline__ void fma2(unsigned long long& d,
                                     unsigned long long a, unsigned long long b) {
    asm("fma.rn.f32x2 %0, %1, %2, %0;" : "+l"(d) : "l"(a), "l"(b));
}

// ---------------- vector float atomic (sm_90+) --------------------------------
__device__ __forceinline__ void red_add_v4(float* addr, float4 v) {
    asm volatile("red.global.add.v4.f32 [%0], {%1,%2,%3,%4};"
                 :: "l"(addr), "f"(v.x), "f"(v.y), "f"(v.z), "f"(v.w) : "memory");
}

// ---------------- zero scratch ------------------------------------------------
__global__ __launch_bounds__(256) void zero_kernel() {
    int i = blockIdx.x * 256 + threadIdx.x;
    const int A1 = N_NODES * IN_DIM;            // 1.2M
    const int A2 = A1 + N_NODES;                // +0.1M
    const int A3 = A2 + N_NODES * EMB;          // +3.2M
    if (i < A1)      g_agg1[i] = 0.f;
    else if (i < A2) g_cnt[i - A1] = 0.f;
    else if (i < A3) g_agg2p[i - A2] = 0.f;
}

// ---------------- scatter layer-1 features + degree counts -------------------
__global__ __launch_bounds__(256) void scatter1_kernel(const void* __restrict__ ei,
                                                       const float* __restrict__ nf) {
    int e = blockIdx.x * 256 + threadIdx.x;
    if (e >= E_MSG) return;
    bool is64 = idx_is64(ei);
    long long s = ld_idx(ei, e, is64);
    long long d = ld_idx(ei, (long long)E_MSG + e, is64);
    const float4* x = (const float4*)(nf + s * IN_DIM);   // 48B rows, 16B aligned
    float* a = g_agg1 + d * IN_DIM;
#pragma unroll
    for (int j = 0; j < 3; j++) red_add_v4(a + 4 * j, x[j]);
    atomicAdd(g_cnt + d, 1.f);
}

// ---------------- SAGE layer 1: 12 -> 64 + LN + relu, fused proj h@Wn2 -------
__global__ __launch_bounds__(256) void sage1_kernel(const float* __restrict__ nf,
                                                    const float* __restrict__ Ws,
                                                    const float* __restrict__ Wn,
                                                    const float* __restrict__ b,
                                                    const float* __restrict__ g,
                                                    const float* __restrict__ be,
                                                    const float* __restrict__ Wn2) {
    __shared__ float sWs[IN_DIM * HID], sWn[IN_DIM * HID], sW2[HID * EMB];
    __shared__ float sb[HID], sg[HID], sbe[HID];
    for (int i = threadIdx.x; i < IN_DIM * HID; i += 256) { sWs[i] = Ws[i]; sWn[i] = Wn[i]; }
    for (int i = threadIdx.x; i < HID * EMB; i += 256) sW2[i] = Wn2[i];
    if (threadIdx.x < HID) {
        sb[threadIdx.x] = b[threadIdx.x];
        sg[threadIdx.x] = g[threadIdx.x];
        sbe[threadIdx.x] = be[threadIdx.x];
    }
    __syncthreads();
    int n = blockIdx.x * 8 + (threadIdx.x >> 5);
    int lane = threadIdx.x & 31;
    float inv = 1.f / fmaxf(g_cnt[n], 1.f);
    float h0 = sb[lane], h1 = sb[lane + 32];
#pragma unroll
    for (int k = 0; k < IN_DIM; k++) {
        float xk = nf[n * IN_DIM + k];
        float ak = g_agg1[n * IN_DIM + k] * inv;
        h0 += xk * sWs[k * HID + lane]      + ak * sWn[k * HID + lane];
        h1 += xk * sWs[k * HID + lane + 32] + ak * sWn[k * HID + lane + 32];
    }
    float s1 = warp_sum(h0 + h1);
    float s2 = warp_sum(h0 * h0 + h1 * h1);
    float mu  = s1 * (1.f / 64.f);
    float var = s2 * (1.f / 64.f) - mu * mu;
    float r = rsqrtf(var + 1e-5f);
    float o0 = fmaxf((h0 - mu) * r * sg[lane]      + sbe[lane],      0.f);
    float o1 = fmaxf((h1 - mu) * r * sg[lane + 32] + sbe[lane + 32], 0.f);
    g_h[n * HID + lane]      = o0;
    g_h[n * HID + lane + 32] = o1;
    // fused projection: p = h @ Wn2 (h is lane-distributed in o0/o1)
    float acc = 0.f;
#pragma unroll
    for (int k = 0; k < 32; k++)
        acc += __shfl_sync(0xffffffffu, o0, k) * sW2[k * EMB + lane];
#pragma unroll
    for (int k = 0; k < 32; k++)
        acc += __shfl_sync(0xffffffffu, o1, k) * sW2[(k + 32) * EMB + lane];
    g_p[n * EMB + lane] = acc;
}

// ---------------- scatter layer-2 (projected): p[src] -> agg2p[dst] ----------
__global__ __launch_bounds__(256) void scatter2_kernel(const void* __restrict__ ei) {
    int e = blockIdx.x * 256 + threadIdx.x;
    if (e >= E_MSG) return;
    bool is64 = idx_is64(ei);
    long long s = ld_idx(ei, e, is64);
    long long d = ld_idx(ei, (long long)E_MSG + e, is64);
    const float4* ps = (const float4*)(g_p + s * EMB);    // 128B rows
    float* pd = g_agg2p + d * EMB;
#pragma unroll
    for (int j = 0; j < 8; j++) red_add_v4(pd + 4 * j, ps[j]);
}

// ---------------- SAGE layer 2: 64 -> 32 + LN + relu -------------------------
__global__ __launch_bounds__(256) void sage2_kernel(const float* __restrict__ Ws,
                                                    const float* __restrict__ b,
                                                    const float* __restrict__ g,
                                                    const float* __restrict__ be) {
    __shared__ float sWs[HID * EMB];
    __shared__ float sb[EMB], sg[EMB], sbe[EMB];
    for (int i = threadIdx.x; i < HID * EMB; i += 256) sWs[i] = Ws[i];
    if (threadIdx.x < EMB) {
        sb[threadIdx.x] = b[threadIdx.x];
        sg[threadIdx.x] = g[threadIdx.x];
        sbe[threadIdx.x] = be[threadIdx.x];
    }
    __syncthreads();
    int n = blockIdx.x * 8 + (threadIdx.x >> 5);
    int lane = threadIdx.x & 31;
    float inv = 1.f / fmaxf(g_cnt[n], 1.f);
    float hl = g_h[n * HID + lane];
    float hh = g_h[n * HID + 32 + lane];
    float acc = sb[lane] + g_agg2p[n * EMB + lane] * inv;
#pragma unroll
    for (int k = 0; k < 32; k++)
        acc += __shfl_sync(0xffffffffu, hl, k) * sWs[k * EMB + lane];
#pragma unroll
    for (int k = 0; k < 32; k++)
        acc += __shfl_sync(0xffffffffu, hh, k) * sWs[(k + 32) * EMB + lane];
    float s1 = warp_sum(acc);
    float s2 = warp_sum(acc * acc);
    float mu  = s1 * (1.f / 32.f);
    float var = s2 * (1.f / 32.f) - mu * mu;
    float r = rsqrtf(var + 1e-5f);
    g_emb[n * EMB + lane] = fmaxf((acc - mu) * r * sg[lane] + sbe[lane], 0.f);
}

// ---------------- fused edge_rep + edge MLP (packed f32x2) -------------------
// Shared layout (floats): W1(74*64) W2(64*32) D1(32*64) D2(64*76) b1(64) b2(32) b3(64) b4(76)
#define SM_W1 0
#define SM_W2 (SM_W1 + EDGE_REPR * HID)
#define SM_D1 (SM_W2 + HID * EMB)
#define SM_D2 (SM_D1 + EMB * HID)
#define SM_B1 (SM_D2 + HID * D2PAD)
#define SM_B2 (SM_B1 + HID)
#define SM_B3 (SM_B2 + EMB)
#define SM_B4 (SM_B3 + HID)
#define SM_TOTAL (SM_B4 + D2PAD)   // 13932 floats = 55728 B

#define MLP_THREADS 128

__global__ __launch_bounds__(MLP_THREADS, 3) void edge_mlp_kernel(
    const void* __restrict__ srcn, const void* __restrict__ dstn,
    const float* __restrict__ ea,
    const float* __restrict__ eW1, const float* __restrict__ eb1,
    const float* __restrict__ eW2, const float* __restrict__ eb2,
    const float* __restrict__ dW1, const float* __restrict__ db1,
    const float* __restrict__ dW2, const float* __restrict__ db2,
    float* __restrict__ out_recon, float* __restrict__ out_er) {
    extern __shared__ float sm[];
    for (int i = threadIdx.x; i < EDGE_REPR * HID; i += MLP_THREADS) sm[SM_W1 + i] = eW1[i];
    for (int i = threadIdx.x; i < HID * EMB; i += MLP_THREADS)       sm[SM_W2 + i] = eW2[i];
    for (int i = threadIdx.x; i < EMB * HID; i += MLP_THREADS)       sm[SM_D1 + i] = dW1[i];
    for (int i = threadIdx.x; i < HID * D2PAD; i += MLP_THREADS) {
        int k = i / D2PAD, j = i - k * D2PAD;
        sm[SM_D2 + i] = (j < EDGE_REPR) ? dW2[k * EDGE_REPR + j] : 0.f;
    }
    for (int i = threadIdx.x; i < HID; i += MLP_THREADS) { sm[SM_B1 + i] = eb1[i]; sm[SM_B3 + i] = db1[i]; }
    for (int i = threadIdx.x; i < EMB; i += MLP_THREADS)   sm[SM_B2 + i] = eb2[i];
    for (int i = threadIdx.x; i < D2PAD; i += MLP_THREADS) sm[SM_B4 + i] = (i < EDGE_REPR) ? db2[i] : 0.f;
    __syncthreads();

    int e = blockIdx.x * MLP_THREADS + threadIdx.x;
    if (e >= E_SC) return;
    bool is64s = idx_is64(srcn);
    bool is64d = idx_is64(dstn);
    long long s = ld_idx(srcn, e, is64s);
    long long d = ld_idx(dstn, e, is64d);

    // -------- gather edge representation --------
    float er[EDGE_REPR];
    {
        const float4* es = (const float4*)(g_emb + s * EMB);
        const float4* ed = (const float4*)(g_emb + d * EMB);
#pragma unroll
        for (int j = 0; j < 8; j++) {
            float4 v = es[j];
            er[4 * j] = v.x; er[4 * j + 1] = v.y; er[4 * j + 2] = v.z; er[4 * j + 3] = v.w;
        }
#pragma unroll
        for (int j = 0; j < 8; j++) {
            float4 v = ed[j];
            er[EMB + 4 * j] = v.x; er[EMB + 4 * j + 1] = v.y;
            er[EMB + 4 * j + 2] = v.z; er[EMB + 4 * j + 3] = v.w;
        }
#pragma unroll
        for (int i = 0; i < EDGE_F; i++) er[2 * EMB + i] = ea[(long long)e * EDGE_F + i];
    }
    // write edge_rep output (8B aligned: e*74*4 % 8 == 0)
    {
        unsigned long long* o = (unsigned long long*)(out_er + (long long)e * EDGE_REPR);
#pragma unroll
        for (int j = 0; j < EDGE_REPR / 2; j++) o[j] = pk2(er[2 * j], er[2 * j + 1]);
    }

    // -------- enc1: 74 -> 64, relu (packed pairs over output dim) --------
    unsigned long long a1[HID / 2];
    {
        const unsigned long long* bp = (const unsigned long long*)(sm + SM_B1);
#pragma unroll
        for (int j = 0; j < HID / 2; j++) a1[j] = bp[j];
#pragma unroll
        for (int k = 0; k < EDGE_REPR; k++) {
            unsigned long long ek = pk2(er[k], er[k]);
            const ulonglong2* w = (const ulonglong2*)(sm + SM_W1 + k * HID);
#pragma unroll
            for (int j = 0; j < HID / 4; j++) {
                ulonglong2 t = w[j];
                fma2(a1[2 * j], ek, t.x);
                fma2(a1[2 * j + 1], ek, t.y);
            }
        }
    }
    float r1[HID];
#pragma unroll
    for (int j = 0; j < HID / 2; j++) upk2(a1[j], r1[2 * j], r1[2 * j + 1]);
#pragma unroll
    for (int j = 0; j < HID; j++) r1[j] = fmaxf(r1[j], 0.f);

    // -------- enc2: 64 -> 32, relu --------
    unsigned long long a2[EMB / 2];
    {
        const unsigned long long* bp = (const unsigned long long*)(sm + SM_B2);
#pragma unroll
        for (int j = 0; j < EMB / 2; j++) a2[j] = bp[j];
#pragma unroll
        for (int k = 0; k < HID; k++) {
            unsigned long long rk = pk2(r1[k], r1[k]);
            const ulonglong2* w = (const ulonglong2*)(sm + SM_W2 + k * EMB);
#pragma unroll
            for (int j = 0; j < EMB / 4; j++) {
                ulonglong2 t = w[j];
                fma2(a2[2 * j], rk, t.x);
                fma2(a2[2 * j + 1], rk, t.y);
            }
        }
    }
    float lat[EMB];
#pragma unroll
    for (int j = 0; j < EMB / 2; j++) upk2(a2[j], lat[2 * j], lat[2 * j + 1]);
#pragma unroll
    for (int j = 0; j < EMB; j++) lat[j] = fmaxf(lat[j], 0.f);

    // -------- dec1: 32 -> 64, relu --------
    unsigned long long a3[HID / 2];
    {
        const unsigned long long* bp = (const unsigned long long*)(sm + SM_B3);
#pragma unroll
        for (int j = 0; j < HID / 2; j++) a3[j] = bp[j];
#pragma unroll
        for (int k = 0; k < EMB; k++) {
            unsigned long long lk = pk2(lat[k], lat[k]);
            const ulonglong2* w = (const ulonglong2*)(sm + SM_D1 + k * HID);
#pragma unroll
            for (int j = 0; j < HID / 4; j++) {
                ulonglong2 t = w[j];
                fma2(a3[2 * j], lk, t.x);
                fma2(a3[2 * j + 1], lk, t.y);
            }
        }
    }
    float h2[HID];
#pragma unroll
    for (int j = 0; j < HID / 2; j++) upk2(a3[j], h2[2 * j], h2[2 * j + 1]);
#pragma unroll
    for (int j = 0; j < HID; j++) h2[j] = fmaxf(h2[j], 0.f);

    // -------- dec2: 64 -> 74 (padded 76), no relu --------
    unsigned long long a4[D2PAD / 2];
    {
        const unsigned long long* bp = (const unsigned long long*)(sm + SM_B4);
#pragma unroll
        for (int j = 0; j < D2PAD / 2; j++) a4[j] = bp[j];
#pragma unroll
        for (int k = 0; k < HID; k++) {
            unsigned long long hk = pk2(h2[k], h2[k]);
            const ulonglong2* w = (const ulonglong2*)(sm + SM_D2 + k * D2PAD);
#pragma unroll
            for (int j = 0; j < D2PAD / 4; j++) {
                ulonglong2 t = w[j];
                fma2(a4[2 * j], hk, t.x);
                fma2(a4[2 * j + 1], hk, t.y);
            }
        }
    }
    {
        unsigned long long* o = (unsigned long long*)(out_recon + (long long)e * EDGE_REPR);
#pragma unroll
        for (int j = 0; j < EDGE_REPR / 2; j++) o[j] = a4[j];  // pairs 0..36 = cols 0..73
    }
}

// ---------------- launcher ----------------------------------------------------
extern "C" void kernel_launch(void* const* d_in, const int* in_sizes, int n_in,
                              void* d_out, int out_size) {
    const float* nf   = (const float*)d_in[0];
    const void*  ei   = d_in[1];
    const float* ea   = (const float*)d_in[2];
    const void*  srcn = d_in[3];
    const void*  dstn = d_in[4];
    const float* Ws1 = (const float*)d_in[5];
    const float* Wn1 = (const float*)d_in[6];
    const float* b1  = (const float*)d_in[7];
    const float* g1  = (const float*)d_in[8];
    const float* be1 = (const float*)d_in[9];
    const float* Ws2 = (const float*)d_in[10];
    const float* Wn2 = (const float*)d_in[11];
    const float* b2  = (const float*)d_in[12];
    const float* g2  = (const float*)d_in[13];
    const float* be2 = (const float*)d_in[14];
    const float* eW1 = (const float*)d_in[15];
    const float* eb1 = (const float*)d_in[16];
    const float* eW2 = (const float*)d_in[17];
    const float* eb2 = (const float*)d_in[18];
    const float* dW1 = (const float*)d_in[19];
    const float* db1 = (const float*)d_in[20];
    const float* dW2 = (const float*)d_in[21];
    const float* db2 = (const float*)d_in[22];

    float* out_recon = (float*)d_out;                                   // [1M, 74]
    float* out_er    = (float*)d_out + (long long)E_SC * EDGE_REPR;     // [1M, 74]

    const int smem_mlp = SM_TOTAL * sizeof(float);  // 55728 B
    cudaFuncSetAttribute(edge_mlp_kernel, cudaFuncAttributeMaxDynamicSharedMemorySize, smem_mlp);

    const int zero_total = N_NODES * IN_DIM + N_NODES + N_NODES * EMB;
    // launch order fixed so edge_mlp is the 6th launch (ncu -s 5 -c 1 profiles it)
    zero_kernel<<<(zero_total + 255) / 256, 256>>>();
    scatter1_kernel<<<(E_MSG + 255) / 256, 256>>>(ei, nf);
    sage1_kernel<<<N_NODES / 8, 256>>>(nf, Ws1, Wn1, b1, g1, be1, Wn2);
    scatter2_kernel<<<(E_MSG + 255) / 256, 256>>>(ei);
    sage2_kernel<<<N_NODES / 8, 256>>>(Ws2, b2, g2, be2);
    edge_mlp_kernel<<<(E_SC + MLP_THREADS - 1) / MLP_THREADS, MLP_THREADS, smem_mlp>>>(
        srcn, dstn, ea, eW1, eb1, eW2, eb2, dW1, db1, dW2, db2, out_recon, out_er);
}